// round 11
// baseline (speedup 1.0000x reference)
#include <cuda_runtime.h>
#include <math.h>

#define R 32
#define PB 36              /* padded smem row stride */
#define L 2048
#define NSEQ 8192
#define NL (NSEQ * L)
#define NL4 (NL / 4)       /* 4194304 */
#define L4 (L / 4)         /* 512     */

#define CSPLIT 48          /* t < 192 -> B path */

#define MAIN_THREADS 512
#define B_BLOCKS 96        /* 96 * 16 warps = 1536 = 48c * 32 n-groups */
#define A_BLOCKS 512       /* each streams a contiguous 128KB region */
#define A_ITEMS 16         /* per thread; 512*512*16 = NL4 */
#define TOTAL_BLOCKS (A_BLOCKS + B_BLOCKS)   /* 608 */

__device__ float    g_A2t[R][L];
__device__ float    g_B2t[R][L];
__device__ float    g_C2[R];
__device__ float    g_D[R];
__device__ int      g_Kt4[L4];
__device__ float    g_partial[TOTAL_BLOCKS];
__device__ unsigned g_count;

__device__ __forceinline__ float ex2f(float x) {
    float y; asm("ex2.approx.f32 %0, %1;" : "=f"(y) : "f"(x)); return y;
}
__device__ __forceinline__ float lg2f_(float x) {
    float y; asm("lg2.approx.f32 %0, %1;" : "=f"(y) : "f"(x)); return y;
}

#define LN2_F 0.69314718055994531f
#define INV_LN2_F 1.44269504088896340f
#define HALF_LOG_2PI 0.91893853320467274f
#define DROP_THRESH (-18.0f)
#define XLO (-8.0f)
#define XHI (8.0f)

// ---------------------------------------------------------------------------
// k_prep: unchanged (proven). 128 blocks x 256 threads; block b emits tables
// for t in [16b,16b+16). h_t == stationary pi for t >= 64 (Doeblin ~0.5).
// ---------------------------------------------------------------------------
__global__ void __launch_bounds__(256) k_prep(const float* __restrict__ Tr,
                                              const float* __restrict__ init_w,
                                              const float* __restrict__ sig,
                                              const float* __restrict__ mu_rates) {
    __shared__ float P[6][R][PB];
    __shared__ float hs[8][R];
    __shared__ float pi_s[R];
    __shared__ int   karr[8];
    const int tid  = threadIdx.x;
    const int w    = tid >> 5, lane = tid & 31;
    const int rw   = tid >> 3, seg = (tid & 7) * 4;
    const int b    = blockIdx.x;

    if (b == 0 && tid == 0) g_count = 0u;

    *(float4*)&P[0][rw][seg] = ((const float4*)Tr)[tid];
    __syncthreads();

    #pragma unroll 1
    for (int k = 1; k < 6; ++k) {
        float4 a0 = make_float4(0.f, 0.f, 0.f, 0.f);
        float4 a1 = make_float4(0.f, 0.f, 0.f, 0.f);
        #pragma unroll
        for (int j = 0; j < R; j += 2) {
            float  r0 = P[k - 1][rw][j];
            float4 b0 = *(const float4*)&P[k - 1][j][seg];
            a0.x = fmaf(r0, b0.x, a0.x); a0.y = fmaf(r0, b0.y, a0.y);
            a0.z = fmaf(r0, b0.z, a0.z); a0.w = fmaf(r0, b0.w, a0.w);
            float  r1 = P[k - 1][rw][j + 1];
            float4 b1 = *(const float4*)&P[k - 1][j + 1][seg];
            a1.x = fmaf(r1, b1.x, a1.x); a1.y = fmaf(r1, b1.y, a1.y);
            a1.z = fmaf(r1, b1.z, a1.z); a1.w = fmaf(r1, b1.w, a1.w);
        }
        float4 acc = make_float4(a0.x + a1.x, a0.y + a1.y, a0.z + a1.z, a0.w + a1.w);
        *(float4*)&P[k][rw][seg] = acc;
        __syncthreads();
    }

    if (w == 0) {
        hs[0][lane] = init_w[lane];
        __syncwarp();
        #pragma unroll 1
        for (int rep = 0; rep < 2; ++rep) {
            float a0 = 0.f, a1 = 0.f, a2 = 0.f, a3 = 0.f;
            #pragma unroll
            for (int j = 0; j < R; j += 4) {
                a0 = fmaf(hs[0][j    ], P[5][j    ][lane], a0);
                a1 = fmaf(hs[0][j + 1], P[5][j + 1][lane], a1);
                a2 = fmaf(hs[0][j + 2], P[5][j + 2][lane], a2);
                a3 = fmaf(hs[0][j + 3], P[5][j + 3][lane], a3);
            }
            float v = (a0 + a1) + (a2 + a3);
            __syncwarp();
            hs[0][lane] = v;
            __syncwarp();
        }
        pi_s[lane] = hs[0][lane];
    }
    __syncthreads();

    float sg     = sig[lane];
    float inv_s2 = 1.0f / (sg * sg);
    float l2sig  = lg2f_(sg);
    float mr     = mu_rates[lane];
    float C2     = -0.5f * inv_s2 * INV_LN2_F;
    if (b == 0 && w == 0) {
        g_C2[lane] = C2;
        g_D[lane]  = mr * inv_s2 * INV_LN2_F;
    }

    int kloc = 1;
    #pragma unroll 1
    for (int i = 0; i < 2; ++i) {
        int t = b * 16 + w * 2 + i;
        if (t < 64) {
            hs[w][lane] = init_w[lane];
            __syncwarp();
            #pragma unroll 1
            for (int k = 0; k < 6; ++k) {
                if ((t >> k) & 1) {
                    float a0 = 0.f, a1 = 0.f, a2 = 0.f, a3 = 0.f;
                    #pragma unroll
                    for (int j = 0; j < R; j += 4) {
                        a0 = fmaf(hs[w][j    ], P[k][j    ][lane], a0);
                        a1 = fmaf(hs[w][j + 1], P[k][j + 1][lane], a1);
                        a2 = fmaf(hs[w][j + 2], P[k][j + 2][lane], a2);
                        a3 = fmaf(hs[w][j + 3], P[k][j + 3][lane], a3);
                    }
                    float v = (a0 + a1) + (a2 + a3);
                    __syncwarp();
                    hs[w][lane] = v;
                    __syncwarp();
                }
            }
        } else {
            hs[w][lane] = pi_s[lane];
            __syncwarp();
        }

        float sum = 0.0f;
        #pragma unroll
        for (int j = 0; j < R; ++j) sum += hs[w][j];
        float lm2 = lg2f_(hs[w][lane]) - lg2f_(sum);

        float mu = (float)t * mr;
        float B2 = mu * inv_s2 * INV_LN2_F;
        float A2 = lm2 - l2sig - 0.5f * mu * mu * inv_s2 * INV_LN2_F;
        g_A2t[lane][t] = A2;
        g_B2t[lane][t] = B2;

        float A0 = __shfl_sync(0xffffffffu, A2, 0);
        float B0 = __shfl_sync(0xffffffffu, B2, 0);
        float C0 = __shfl_sync(0xffffffffu, C2, 0);
        float dA = A2 - A0, dB = B2 - B0, dC = C2 - C0;
        float d1 = dA + dB * XLO + dC * XLO * XLO;
        float d2 = dA + dB * XHI + dC * XHI * XHI;
        float dmax = fmaxf(d1, d2);
        if (fabsf(dC) > 1e-20f) {
            float xv = -dB / (2.0f * dC);
            if (xv > XLO && xv < XHI) dmax = fmaxf(dmax, dA + dB * xv + dC * xv * xv);
        }
        bool keep = (dmax >= DROP_THRESH);
        unsigned bm = __ballot_sync(0xffffffffu, keep);
        int K = 32 - __clz(bm);
        kloc = max(kloc, K);
    }
    if (lane == 0) karr[w] = kloc;
    __syncthreads();
    if (tid < 4) {
        g_Kt4[b * 4 + tid] = max(karr[2 * tid], karr[2 * tid + 1]);
    }
}

// ---------------------------------------------------------------------------
// Robust per-element logsumexp (cold fallbacks only)
// ---------------------------------------------------------------------------
__device__ __noinline__ float robust_lp(float x, float q, int t, int K) {
    float m = -3.0e38f;
    for (int r = 0; r < K; ++r) {
        float arg = fmaf(g_C2[r], q, fmaf(g_B2t[r][t], x, g_A2t[r][t]));
        m = fmaxf(m, arg);
    }
    float s = 0.0f;
    for (int r = 0; r < K; ++r) {
        float arg = fmaf(g_C2[r], q, fmaf(g_B2t[r][t], x, g_A2t[r][t]));
        s += ex2f(arg - m);
    }
    return LN2_F * (m + lg2f_(s));
}

// Cold A handler (provably unreachable for c>=48; kept for safety).
__device__ __noinline__ float coldA(const float4* __restrict__ X4,
                                    int base, int c, int K) {
    float acc = 0.0f;
    for (int k = 0; k < A_ITEMS; ++k) {
        float4 xv = X4[base + k * MAIN_THREADS];
        int t0 = c * 4;
        acc += robust_lp(xv.x, xv.x * xv.x, t0,     K);
        acc += robust_lp(xv.y, xv.y * xv.y, t0 + 1, K);
        acc += robust_lp(xv.z, xv.z * xv.z, t0 + 2, K);
        acc += robust_lp(xv.w, xv.w * xv.w, t0 + 3, K);
    }
    return acc - (float)(4 * A_ITEMS) * HALF_LOG_2PI;
}

// ---------------------------------------------------------------------------
// Fused main, 512 threads/block. Blocks [0,96): B path (t<192), c-coherent
// warps, balanced interleave, MUFU ex2. Blocks [96,608): A path — block b
// streams the CONTIGUOUS region [8192b, 8192(b+1)) of X4 sequentially
// (DRAM row locality), thread th has fixed c = th, double-buffered batches
// of 4 keep loads continuously in flight. th<48 lanes masked (B owns them).
// Deterministic fused fixed-order tail.
// ---------------------------------------------------------------------------
__global__ void __launch_bounds__(MAIN_THREADS) k_main(const float* __restrict__ X,
                                                       float* __restrict__ out) {
    __shared__ float4 sA[R][CSPLIT];
    __shared__ float  sD[R], sC[R];
    __shared__ int    sK[CSPLIT];
    __shared__ float  sred[MAIN_THREADS];
    __shared__ bool   s_last;

    const float4* X4 = (const float4*)X;
    const float4* A4 = (const float4*)g_A2t;
    const int th = threadIdx.x;
    float acc = 0.0f;

    if (blockIdx.x < B_BLOCKS) {
        // ---------------- B path: t < 192 ----------------
        #pragma unroll
        for (int j = 0; j < (R * CSPLIT + MAIN_THREADS - 1) / MAIN_THREADS; ++j) {
            int e = th + j * MAIN_THREADS;
            if (e < R * CSPLIT) {
                int r = e / CSPLIT, c = e - r * CSPLIT;
                sA[r][c] = A4[r * L4 + c];
            }
        }
        if (th < R) { sD[th] = g_D[th]; sC[th] = g_C2[th]; }
        if (th < CSPLIT) sK[th] = g_Kt4[th];
        __syncthreads();

        const int lane = th & 31;
        const int W = blockIdx.x * 16 + (th >> 5);   // 0..1535
        const int idx = W % CSPLIT;
        const int c = (idx & 1) ? (CSPLIT - 1 - (idx >> 1)) : (idx >> 1);
        const int ng = W / CSPLIT;                   // 0..31

        float4 xv[8];
        #pragma unroll
        for (int it = 0; it < 8; ++it) {
            int n = ng * 256 + it * 32 + lane;
            xv[it] = __ldcs(&X4[n * L4 + c]);
        }

        const int K = sK[c];
        const float t0f = (float)(4 * c);

        #pragma unroll 1
        for (int it = 0; it < 8; ++it) {
            float x0 = xv[it].x, x1 = xv[it].y, x2 = xv[it].z, x3 = xv[it].w;
            float q0 = x0 * x0, q1 = x1 * x1, q2 = x2 * x2, q3 = x3 * x3;
            float S0 = 0.f, S1 = 0.f, S2 = 0.f, S3 = 0.f;
            #pragma unroll 2
            for (int r = 0; r < K; ++r) {
                float4 ar = sA[r][c];
                float d  = sD[r];
                float cr = sC[r];
                float b0 = d * t0f, b1 = b0 + d, b2 = b1 + d, b3 = b2 + d;
                S0 += ex2f(fmaf(cr, q0, fmaf(b0, x0, ar.x)));
                S1 += ex2f(fmaf(cr, q1, fmaf(b1, x1, ar.y)));
                S2 += ex2f(fmaf(cr, q2, fmaf(b2, x2, ar.z)));
                S3 += ex2f(fmaf(cr, q3, fmaf(b3, x3, ar.w)));
            }
            float smin = fminf(fminf(S0, S1), fminf(S2, S3));
            if (smin > 1e-30f) {
                acc += LN2_F * (lg2f_(S0) + lg2f_(S1) + lg2f_(S2) + lg2f_(S3));
            } else {
                int tt = c * 4;
                acc += robust_lp(x0, q0, tt,     K);
                acc += robust_lp(x1, q1, tt + 1, K);
                acc += robust_lp(x2, q2, tt + 2, K);
                acc += robust_lp(x3, q3, tt + 3, K);
            }
            acc -= 4.0f * HALF_LOG_2PI;
        }
    } else {
        // ---------------- A path: contiguous streaming, c = th ----------------
        const float4* B4 = (const float4*)g_B2t;
        const int b    = blockIdx.x - B_BLOCKS;                 // 0..511
        const int base = b * (MAIN_THREADS * A_ITEMS) + th;     // 8192*b + th
        const int K    = g_Kt4[th];                             // c == th

        if (th >= CSPLIT && K != 1) {
            acc = coldA(X4, base, th, K);        // unreachable safety path
        } else {
            const float4 a  = A4[th];
            const float4 bb = B4[th];
            const float  cc = g_C2[0];

            float4 u[4], v[4];
            #pragma unroll
            for (int j = 0; j < 4; ++j)
                u[j] = __ldcs(&X4[base + j * MAIN_THREADS]);

            float s = 0.0f;
            #pragma unroll
            for (int seg = 0; seg < 4; ++seg) {
                float4* cur = (seg & 1) ? v : u;
                float4* nxt = (seg & 1) ? u : v;
                if (seg < 3) {
                    #pragma unroll
                    for (int j = 0; j < 4; ++j)
                        nxt[j] = __ldcs(&X4[base + ((seg + 1) * 4 + j) * MAIN_THREADS]);
                }
                #pragma unroll
                for (int j = 0; j < 4; ++j) {
                    float x0 = cur[j].x, x1 = cur[j].y, x2 = cur[j].z, x3 = cur[j].w;
                    float g0 = fmaf(cc, x0 * x0, fmaf(bb.x, x0, a.x));
                    float g1 = fmaf(cc, x1 * x1, fmaf(bb.y, x1, a.y));
                    float g2 = fmaf(cc, x2 * x2, fmaf(bb.z, x2, a.z));
                    float g3 = fmaf(cc, x3 * x3, fmaf(bb.w, x3, a.w));
                    s += (g0 + g1) + (g2 + g3);
                }
            }
            // th < CSPLIT lanes: their c belongs to the B path -> masked out.
            float we = (th >= CSPLIT) ? 1.0f : 0.0f;
            acc = we * (LN2_F * s - (float)(4 * A_ITEMS) * HALF_LOG_2PI);
        }
        __syncthreads();   // mirror B path's post-load sync (uniform per block)
    }

    // ---------------- fused deterministic tail ----------------
    sred[th] = acc;
    __syncthreads();
    for (int s = MAIN_THREADS / 2; s > 0; s >>= 1) {
        if (th < s) sred[th] += sred[th + s];
        __syncthreads();
    }
    if (th == 0) {
        g_partial[blockIdx.x] = sred[0];
        __threadfence();
        unsigned n = atomicAdd(&g_count, 1u);
        s_last = (n == TOTAL_BLOCKS - 1);
    }
    __syncthreads();

    if (s_last) {
        __threadfence();
        float v = g_partial[th];
        if (th < TOTAL_BLOCKS - MAIN_THREADS) v += g_partial[MAIN_THREADS + th];
        sred[th] = v;
        __syncthreads();
        for (int s = MAIN_THREADS / 2; s > 0; s >>= 1) {
            if (th < s) sred[th] += sred[th + s];
            __syncthreads();
        }
        if (th == 0) out[0] = sred[0] / (float)NSEQ;
    }
}

// ---------------------------------------------------------------------------
extern "C" void kernel_launch(void* const* d_in, const int* in_sizes, int n_in,
                              void* d_out, int out_size) {
    const float* X       = (const float*)d_in[0];
    const float* Tr      = (const float*)d_in[1];
    const float* init_w  = (const float*)d_in[2];
    const float* sig     = (const float*)d_in[3];
    const float* mu_rate = (const float*)d_in[4];
    float* out = (float*)d_out;

    k_prep<<<128, 256>>>(Tr, init_w, sig, mu_rate);
    k_main<<<TOTAL_BLOCKS, MAIN_THREADS>>>(X, out);
}

// round 12
// speedup vs baseline: 1.2435x; 1.2435x over previous
#include <cuda_runtime.h>
#include <math.h>

#define R 32
#define PB 36              /* padded smem row stride */
#define L 2048
#define NSEQ 8192
#define NL (NSEQ * L)
#define NL4 (NL / 4)       /* 4194304 */
#define L4 (L / 4)         /* 512     */

#define CSPLIT 48          /* t < 192 -> B path */

#define THREADS 256
#define PREP_BLOCKS 128    /* resident in wave 1 -> flag always satisfiable */
#define B_BLOCKS 192
#define A_BLOCKS 2048
#define A_ITEMS 8          /* 2048*256*8 = NL4 */
#define A_STRIDE (A_BLOCKS * THREADS)   /* 524288, multiple of L4 */
#define TOTAL_BLOCKS (B_BLOCKS + A_BLOCKS)   /* 2240 */

#define SBUF_BYTES 27648   /* max(prep P: 6*32*36*4 = 27648, sA: 24576) */

__device__ float    g_A2t[R][L];
__device__ float    g_B2t[R][L];
__device__ float    g_C2[R];
__device__ float    g_D[R];
__device__ int      g_Kt4[L4];
__device__ float    g_partial[TOTAL_BLOCKS];
__device__ unsigned g_count = 0u;
__device__ unsigned g_ready = 0u;

__device__ __forceinline__ float ex2f(float x) {
    float y; asm("ex2.approx.f32 %0, %1;" : "=f"(y) : "f"(x)); return y;
}
__device__ __forceinline__ float lg2f_(float x) {
    float y; asm("lg2.approx.f32 %0, %1;" : "=f"(y) : "f"(x)); return y;
}

#define LN2_F 0.69314718055994531f
#define INV_LN2_F 1.44269504088896340f
#define HALF_LOG_2PI 0.91893853320467274f
#define DROP_THRESH (-18.0f)
#define XLO (-8.0f)
#define XHI (8.0f)

// ---------------------------------------------------------------------------
// Prep phase (device function): block b emits tables for t in [16b, 16b+16).
// Identical math to the proven k_prep. P (squaring buffers) aliases sbuf.
// Ends with release: per-thread fence, block sync, one atomicAdd on g_ready.
// ---------------------------------------------------------------------------
__device__ void do_prep(float (*P)[R][PB],
                        const float* __restrict__ Tr,
                        const float* __restrict__ init_w,
                        const float* __restrict__ sig,
                        const float* __restrict__ mu_rates, int b) {
    __shared__ float hs[8][R];
    __shared__ float pi_s[R];
    __shared__ int   karr[8];
    const int tid  = threadIdx.x;
    const int w    = tid >> 5, lane = tid & 31;
    const int rw   = tid >> 3, seg = (tid & 7) * 4;

    *(float4*)&P[0][rw][seg] = ((const float4*)Tr)[tid];
    __syncthreads();

    #pragma unroll 1
    for (int k = 1; k < 6; ++k) {
        float4 a0 = make_float4(0.f, 0.f, 0.f, 0.f);
        float4 a1 = make_float4(0.f, 0.f, 0.f, 0.f);
        #pragma unroll
        for (int j = 0; j < R; j += 2) {
            float  r0 = P[k - 1][rw][j];
            float4 b0 = *(const float4*)&P[k - 1][j][seg];
            a0.x = fmaf(r0, b0.x, a0.x); a0.y = fmaf(r0, b0.y, a0.y);
            a0.z = fmaf(r0, b0.z, a0.z); a0.w = fmaf(r0, b0.w, a0.w);
            float  r1 = P[k - 1][rw][j + 1];
            float4 b1 = *(const float4*)&P[k - 1][j + 1][seg];
            a1.x = fmaf(r1, b1.x, a1.x); a1.y = fmaf(r1, b1.y, a1.y);
            a1.z = fmaf(r1, b1.z, a1.z); a1.w = fmaf(r1, b1.w, a1.w);
        }
        float4 acc = make_float4(a0.x + a1.x, a0.y + a1.y, a0.z + a1.z, a0.w + a1.w);
        *(float4*)&P[k][rw][seg] = acc;
        __syncthreads();
    }

    if (w == 0) {
        hs[0][lane] = init_w[lane];
        __syncwarp();
        #pragma unroll 1
        for (int rep = 0; rep < 2; ++rep) {
            float a0 = 0.f, a1 = 0.f, a2 = 0.f, a3 = 0.f;
            #pragma unroll
            for (int j = 0; j < R; j += 4) {
                a0 = fmaf(hs[0][j    ], P[5][j    ][lane], a0);
                a1 = fmaf(hs[0][j + 1], P[5][j + 1][lane], a1);
                a2 = fmaf(hs[0][j + 2], P[5][j + 2][lane], a2);
                a3 = fmaf(hs[0][j + 3], P[5][j + 3][lane], a3);
            }
            float v = (a0 + a1) + (a2 + a3);
            __syncwarp();
            hs[0][lane] = v;
            __syncwarp();
        }
        pi_s[lane] = hs[0][lane];
    }
    __syncthreads();

    float sg     = sig[lane];
    float inv_s2 = 1.0f / (sg * sg);
    float l2sig  = lg2f_(sg);
    float mr     = mu_rates[lane];
    float C2     = -0.5f * inv_s2 * INV_LN2_F;
    if (b == 0 && w == 0) {
        g_C2[lane] = C2;
        g_D[lane]  = mr * inv_s2 * INV_LN2_F;
    }

    int kloc = 1;
    #pragma unroll 1
    for (int i = 0; i < 2; ++i) {
        int t = b * 16 + w * 2 + i;
        if (t < 64) {
            hs[w][lane] = init_w[lane];
            __syncwarp();
            #pragma unroll 1
            for (int k = 0; k < 6; ++k) {
                if ((t >> k) & 1) {
                    float a0 = 0.f, a1 = 0.f, a2 = 0.f, a3 = 0.f;
                    #pragma unroll
                    for (int j = 0; j < R; j += 4) {
                        a0 = fmaf(hs[w][j    ], P[k][j    ][lane], a0);
                        a1 = fmaf(hs[w][j + 1], P[k][j + 1][lane], a1);
                        a2 = fmaf(hs[w][j + 2], P[k][j + 2][lane], a2);
                        a3 = fmaf(hs[w][j + 3], P[k][j + 3][lane], a3);
                    }
                    float v = (a0 + a1) + (a2 + a3);
                    __syncwarp();
                    hs[w][lane] = v;
                    __syncwarp();
                }
            }
        } else {
            hs[w][lane] = pi_s[lane];
            __syncwarp();
        }

        float sum = 0.0f;
        #pragma unroll
        for (int j = 0; j < R; ++j) sum += hs[w][j];
        float lm2 = lg2f_(hs[w][lane]) - lg2f_(sum);

        float mu = (float)t * mr;
        float B2 = mu * inv_s2 * INV_LN2_F;
        float A2 = lm2 - l2sig - 0.5f * mu * mu * inv_s2 * INV_LN2_F;
        g_A2t[lane][t] = A2;
        g_B2t[lane][t] = B2;

        float A0 = __shfl_sync(0xffffffffu, A2, 0);
        float B0 = __shfl_sync(0xffffffffu, B2, 0);
        float C0 = __shfl_sync(0xffffffffu, C2, 0);
        float dA = A2 - A0, dB = B2 - B0, dC = C2 - C0;
        float d1 = dA + dB * XLO + dC * XLO * XLO;
        float d2 = dA + dB * XHI + dC * XHI * XHI;
        float dmax = fmaxf(d1, d2);
        if (fabsf(dC) > 1e-20f) {
            float xv = -dB / (2.0f * dC);
            if (xv > XLO && xv < XHI) dmax = fmaxf(dmax, dA + dB * xv + dC * xv * xv);
        }
        bool keep = (dmax >= DROP_THRESH);
        unsigned bm = __ballot_sync(0xffffffffu, keep);
        int K = 32 - __clz(bm);
        kloc = max(kloc, K);
    }
    if (lane == 0) karr[w] = kloc;
    __syncthreads();
    if (tid < 4)
        g_Kt4[b * 4 + tid] = max(karr[2 * tid], karr[2 * tid + 1]);

    // release: all table stores visible, then count this block as done
    __threadfence();
    __syncthreads();
    if (tid == 0) atomicAdd(&g_ready, 1u);
}

// ---------------------------------------------------------------------------
// Robust per-element logsumexp (cold fallbacks only)
// ---------------------------------------------------------------------------
__device__ __noinline__ float robust_lp(float x, float q, int t, int K) {
    float m = -3.0e38f;
    for (int r = 0; r < K; ++r) {
        float arg = fmaf(g_C2[r], q, fmaf(g_B2t[r][t], x, g_A2t[r][t]));
        m = fmaxf(m, arg);
    }
    float s = 0.0f;
    for (int r = 0; r < K; ++r) {
        float arg = fmaf(g_C2[r], q, fmaf(g_B2t[r][t], x, g_A2t[r][t]));
        s += ex2f(arg - m);
    }
    return LN2_F * (m + lg2f_(s));
}

// Cold A handler (provably unreachable for c>=48; kept for safety).
__device__ __noinline__ float coldA(const float4* __restrict__ X4,
                                    int tid, int c, int K) {
    float acc = 0.0f;
    for (int k = 0; k < A_ITEMS; ++k) {
        float4 xv = X4[tid + k * A_STRIDE];
        int t0 = c * 4;
        acc += robust_lp(xv.x, xv.x * xv.x, t0,     K);
        acc += robust_lp(xv.y, xv.y * xv.y, t0 + 1, K);
        acc += robust_lp(xv.z, xv.z * xv.z, t0 + 2, K);
        acc += robust_lp(xv.w, xv.w * xv.w, t0 + 3, K);
    }
    return acc - (float)(4 * A_ITEMS) * HALF_LOG_2PI;
}

// ---------------------------------------------------------------------------
// Single fused kernel. Blocks [0,128): prep phase first (wave-1 resident).
// Blocks [0,192): B path (t<192) — issue X gathers, wait for tables, compute
// with smem A-table + MUFU ex2. Blocks [192,2240): A path — issue 8 coalesced
// X preloads IMMEDIATELY (no table dependency), spin on g_ready, then the
// K==1 pure-FMA path. Deterministic fixed-order tail; counters reset by the
// final block for graph-replay safety.
// ---------------------------------------------------------------------------
__global__ void __launch_bounds__(THREADS) k_all(const float* __restrict__ X,
                                                 const float* __restrict__ Tr,
                                                 const float* __restrict__ init_w,
                                                 const float* __restrict__ sig,
                                                 const float* __restrict__ mu_rates,
                                                 float* __restrict__ out) {
    __shared__ __align__(16) char sbuf[SBUF_BYTES];
    __shared__ float sD[R], sC[R];
    __shared__ int   sK[CSPLIT];
    __shared__ float sred[THREADS];
    __shared__ bool  s_last;

    const int th  = threadIdx.x;
    const int bid = blockIdx.x;
    const float4* X4 = (const float4*)X;
    const float4* A4 = (const float4*)g_A2t;
    float acc = 0.0f;

    if (bid < PREP_BLOCKS)
        do_prep((float (*)[R][PB])sbuf, Tr, init_w, sig, mu_rates, bid);

    if (bid < B_BLOCKS) {
        // ---------------- B path: t < 192 ----------------
        const int lane = th & 31;
        const int W = bid * 8 + (th >> 5);           // 0..1535
        const int idx = W % CSPLIT;
        const int c = (idx & 1) ? (CSPLIT - 1 - (idx >> 1)) : (idx >> 1);
        const int ng = W / CSPLIT;                   // 0..31

        float4 xv[8];
        #pragma unroll
        for (int it = 0; it < 8; ++it) {
            int n = ng * 256 + it * 32 + lane;
            xv[it] = __ldcs(&X4[n * L4 + c]);
        }

        if (th == 0) {
            while (*((volatile unsigned*)&g_ready) < PREP_BLOCKS) __nanosleep(64);
        }
        __syncthreads();
        __threadfence();

        float4 (*sA)[CSPLIT] = (float4 (*)[CSPLIT])sbuf;
        #pragma unroll
        for (int j = 0; j < (R * CSPLIT + THREADS - 1) / THREADS; ++j) {
            int e = th + j * THREADS;
            if (e < R * CSPLIT) {
                int r = e / CSPLIT, cc2 = e - r * CSPLIT;
                sA[r][cc2] = A4[r * L4 + cc2];
            }
        }
        if (th < R) { sD[th] = g_D[th]; sC[th] = g_C2[th]; }
        if (th < CSPLIT) sK[th] = g_Kt4[th];
        __syncthreads();

        const int K = sK[c];
        const float t0f = (float)(4 * c);

        #pragma unroll 1
        for (int it = 0; it < 8; ++it) {
            float x0 = xv[it].x, x1 = xv[it].y, x2 = xv[it].z, x3 = xv[it].w;
            float q0 = x0 * x0, q1 = x1 * x1, q2 = x2 * x2, q3 = x3 * x3;
            float S0 = 0.f, S1 = 0.f, S2 = 0.f, S3 = 0.f;
            #pragma unroll 2
            for (int r = 0; r < K; ++r) {
                float4 ar = sA[r][c];
                float d  = sD[r];
                float cr = sC[r];
                float b0 = d * t0f, b1 = b0 + d, b2 = b1 + d, b3 = b2 + d;
                S0 += ex2f(fmaf(cr, q0, fmaf(b0, x0, ar.x)));
                S1 += ex2f(fmaf(cr, q1, fmaf(b1, x1, ar.y)));
                S2 += ex2f(fmaf(cr, q2, fmaf(b2, x2, ar.z)));
                S3 += ex2f(fmaf(cr, q3, fmaf(b3, x3, ar.w)));
            }
            float smin = fminf(fminf(S0, S1), fminf(S2, S3));
            if (smin > 1e-30f) {
                acc += LN2_F * (lg2f_(S0) + lg2f_(S1) + lg2f_(S2) + lg2f_(S3));
            } else {
                int tt = c * 4;
                acc += robust_lp(x0, q0, tt,     K);
                acc += robust_lp(x1, q1, tt + 1, K);
                acc += robust_lp(x2, q2, tt + 2, K);
                acc += robust_lp(x3, q3, tt + 3, K);
            }
            acc -= 4.0f * HALF_LOG_2PI;
        }
    } else {
        // ---------------- A path: t >= 192, K == 1 ----------------
        const float4* B4 = (const float4*)g_B2t;
        const int tid = (bid - B_BLOCKS) * THREADS + th;
        const int c = tid & (L4 - 1);

        float4 xv[A_ITEMS];
        if (c >= CSPLIT) {
            #pragma unroll
            for (int k = 0; k < A_ITEMS; ++k)
                xv[k] = __ldcs(&X4[tid + k * A_STRIDE]);
        }

        if (th == 0) {
            while (*((volatile unsigned*)&g_ready) < PREP_BLOCKS) __nanosleep(64);
        }
        __syncthreads();
        __threadfence();

        if (c >= CSPLIT) {
            const int K = g_Kt4[c];
            if (K == 1) {
                const float4 a = A4[c];
                const float4 b = B4[c];
                const float cc = g_C2[0];
                float s = 0.0f;
                #pragma unroll
                for (int k = 0; k < A_ITEMS; ++k) {
                    float x0 = xv[k].x, x1 = xv[k].y, x2 = xv[k].z, x3 = xv[k].w;
                    float g0 = fmaf(cc, x0 * x0, fmaf(b.x, x0, a.x));
                    float g1 = fmaf(cc, x1 * x1, fmaf(b.y, x1, a.y));
                    float g2 = fmaf(cc, x2 * x2, fmaf(b.z, x2, a.z));
                    float g3 = fmaf(cc, x3 * x3, fmaf(b.w, x3, a.w));
                    s += (g0 + g1) + (g2 + g3);
                }
                acc = LN2_F * s - (float)(4 * A_ITEMS) * HALF_LOG_2PI;
            } else {
                acc = coldA(X4, tid, c, K);   // unreachable safety path
            }
        }
    }

    // ---------------- fused deterministic tail ----------------
    sred[th] = acc;
    __syncthreads();
    for (int s = THREADS / 2; s > 0; s >>= 1) {
        if (th < s) sred[th] += sred[th + s];
        __syncthreads();
    }
    if (th == 0) {
        g_partial[bid] = sred[0];
        __threadfence();
        unsigned n = atomicAdd(&g_count, 1u);
        s_last = (n == TOTAL_BLOCKS - 1);
    }
    __syncthreads();

    if (s_last) {
        __threadfence();
        float v = 0.0f;
        for (int idx = th; idx < TOTAL_BLOCKS; idx += THREADS)
            v += g_partial[idx];
        sred[th] = v;
        __syncthreads();
        for (int s = THREADS / 2; s > 0; s >>= 1) {
            if (th < s) sred[th] += sred[th + s];
            __syncthreads();
        }
        if (th == 0) {
            out[0] = sred[0] / (float)NSEQ;
            __threadfence();
            g_count = 0u;            // graph-replay reset
            g_ready = 0u;
        }
    }
}

// ---------------------------------------------------------------------------
extern "C" void kernel_launch(void* const* d_in, const int* in_sizes, int n_in,
                              void* d_out, int out_size) {
    const float* X       = (const float*)d_in[0];
    const float* Tr      = (const float*)d_in[1];
    const float* init_w  = (const float*)d_in[2];
    const float* sig     = (const float*)d_in[3];
    const float* mu_rate = (const float*)d_in[4];
    float* out = (float*)d_out;

    k_all<<<TOTAL_BLOCKS, THREADS>>>(X, Tr, init_w, sig, mu_rate, out);
}

// round 13
// speedup vs baseline: 1.3276x; 1.0676x over previous
#include <cuda_runtime.h>
#include <math.h>

#define R 32
#define PB 36              /* padded smem row stride */
#define L 2048
#define NSEQ 8192
#define NL (NSEQ * L)
#define NL4 (NL / 4)       /* 4194304 */
#define L4 (L / 4)         /* 512     */

#define CSPLIT 48          /* t < 192 -> B path */

#define THREADS 256
#define B_BLOCKS 192
#define A_BLOCKS 512
#define A_ITEMS 32         /* 512*256*32 = NL4 */
#define A_STRIDE (A_BLOCKS * THREADS)   /* 131072, multiple of L4 */
#define TOTAL_BLOCKS (B_BLOCKS + A_BLOCKS)   /* 704 */

__device__ float    g_A2t[R][L];
__device__ float    g_B2t[R][L];
__device__ float    g_C2[R];
__device__ float    g_D[R];
__device__ int      g_Kt4[L4];
__device__ float    g_partial[TOTAL_BLOCKS];
__device__ unsigned g_count;

__device__ __forceinline__ float ex2f(float x) {
    float y; asm("ex2.approx.f32 %0, %1;" : "=f"(y) : "f"(x)); return y;
}
__device__ __forceinline__ float lg2f_(float x) {
    float y; asm("lg2.approx.f32 %0, %1;" : "=f"(y) : "f"(x)); return y;
}

#define LN2_F 0.69314718055994531f
#define INV_LN2_F 1.44269504088896340f
#define HALF_LOG_2PI 0.91893853320467274f
#define DROP_THRESH (-18.0f)
#define XLO (-8.0f)
#define XHI (8.0f)

// ---------------------------------------------------------------------------
// k_prep: proven. 128 blocks x 256 threads; block b emits tables for t in
// [16b,16b+16). h_t == stationary pi for t >= 64 (Doeblin ~0.5).
// ---------------------------------------------------------------------------
__global__ void __launch_bounds__(256) k_prep(const float* __restrict__ Tr,
                                              const float* __restrict__ init_w,
                                              const float* __restrict__ sig,
                                              const float* __restrict__ mu_rates) {
    __shared__ float P[6][R][PB];
    __shared__ float hs[8][R];
    __shared__ float pi_s[R];
    __shared__ int   karr[8];
    const int tid  = threadIdx.x;
    const int w    = tid >> 5, lane = tid & 31;
    const int rw   = tid >> 3, seg = (tid & 7) * 4;
    const int b    = blockIdx.x;

    if (b == 0 && tid == 0) g_count = 0u;

    *(float4*)&P[0][rw][seg] = ((const float4*)Tr)[tid];
    __syncthreads();

    #pragma unroll 1
    for (int k = 1; k < 6; ++k) {
        float4 a0 = make_float4(0.f, 0.f, 0.f, 0.f);
        float4 a1 = make_float4(0.f, 0.f, 0.f, 0.f);
        #pragma unroll
        for (int j = 0; j < R; j += 2) {
            float  r0 = P[k - 1][rw][j];
            float4 b0 = *(const float4*)&P[k - 1][j][seg];
            a0.x = fmaf(r0, b0.x, a0.x); a0.y = fmaf(r0, b0.y, a0.y);
            a0.z = fmaf(r0, b0.z, a0.z); a0.w = fmaf(r0, b0.w, a0.w);
            float  r1 = P[k - 1][rw][j + 1];
            float4 b1 = *(const float4*)&P[k - 1][j + 1][seg];
            a1.x = fmaf(r1, b1.x, a1.x); a1.y = fmaf(r1, b1.y, a1.y);
            a1.z = fmaf(r1, b1.z, a1.z); a1.w = fmaf(r1, b1.w, a1.w);
        }
        float4 acc = make_float4(a0.x + a1.x, a0.y + a1.y, a0.z + a1.z, a0.w + a1.w);
        *(float4*)&P[k][rw][seg] = acc;
        __syncthreads();
    }

    if (w == 0) {
        hs[0][lane] = init_w[lane];
        __syncwarp();
        #pragma unroll 1
        for (int rep = 0; rep < 2; ++rep) {
            float a0 = 0.f, a1 = 0.f, a2 = 0.f, a3 = 0.f;
            #pragma unroll
            for (int j = 0; j < R; j += 4) {
                a0 = fmaf(hs[0][j    ], P[5][j    ][lane], a0);
                a1 = fmaf(hs[0][j + 1], P[5][j + 1][lane], a1);
                a2 = fmaf(hs[0][j + 2], P[5][j + 2][lane], a2);
                a3 = fmaf(hs[0][j + 3], P[5][j + 3][lane], a3);
            }
            float v = (a0 + a1) + (a2 + a3);
            __syncwarp();
            hs[0][lane] = v;
            __syncwarp();
        }
        pi_s[lane] = hs[0][lane];
    }
    __syncthreads();

    float sg     = sig[lane];
    float inv_s2 = 1.0f / (sg * sg);
    float l2sig  = lg2f_(sg);
    float mr     = mu_rates[lane];
    float C2     = -0.5f * inv_s2 * INV_LN2_F;
    if (b == 0 && w == 0) {
        g_C2[lane] = C2;
        g_D[lane]  = mr * inv_s2 * INV_LN2_F;
    }

    int kloc = 1;
    #pragma unroll 1
    for (int i = 0; i < 2; ++i) {
        int t = b * 16 + w * 2 + i;
        if (t < 64) {
            hs[w][lane] = init_w[lane];
            __syncwarp();
            #pragma unroll 1
            for (int k = 0; k < 6; ++k) {
                if ((t >> k) & 1) {
                    float a0 = 0.f, a1 = 0.f, a2 = 0.f, a3 = 0.f;
                    #pragma unroll
                    for (int j = 0; j < R; j += 4) {
                        a0 = fmaf(hs[w][j    ], P[k][j    ][lane], a0);
                        a1 = fmaf(hs[w][j + 1], P[k][j + 1][lane], a1);
                        a2 = fmaf(hs[w][j + 2], P[k][j + 2][lane], a2);
                        a3 = fmaf(hs[w][j + 3], P[k][j + 3][lane], a3);
                    }
                    float v = (a0 + a1) + (a2 + a3);
                    __syncwarp();
                    hs[w][lane] = v;
                    __syncwarp();
                }
            }
        } else {
            hs[w][lane] = pi_s[lane];
            __syncwarp();
        }

        float sum = 0.0f;
        #pragma unroll
        for (int j = 0; j < R; ++j) sum += hs[w][j];
        float lm2 = lg2f_(hs[w][lane]) - lg2f_(sum);

        float mu = (float)t * mr;
        float B2 = mu * inv_s2 * INV_LN2_F;
        float A2 = lm2 - l2sig - 0.5f * mu * mu * inv_s2 * INV_LN2_F;
        g_A2t[lane][t] = A2;
        g_B2t[lane][t] = B2;

        float A0 = __shfl_sync(0xffffffffu, A2, 0);
        float B0 = __shfl_sync(0xffffffffu, B2, 0);
        float C0 = __shfl_sync(0xffffffffu, C2, 0);
        float dA = A2 - A0, dB = B2 - B0, dC = C2 - C0;
        float d1 = dA + dB * XLO + dC * XLO * XLO;
        float d2 = dA + dB * XHI + dC * XHI * XHI;
        float dmax = fmaxf(d1, d2);
        if (fabsf(dC) > 1e-20f) {
            float xv = -dB / (2.0f * dC);
            if (xv > XLO && xv < XHI) dmax = fmaxf(dmax, dA + dB * xv + dC * xv * xv);
        }
        bool keep = (dmax >= DROP_THRESH);
        unsigned bm = __ballot_sync(0xffffffffu, keep);
        int K = 32 - __clz(bm);
        kloc = max(kloc, K);
    }
    if (lane == 0) karr[w] = kloc;
    __syncthreads();
    if (tid < 4)
        g_Kt4[b * 4 + tid] = max(karr[2 * tid], karr[2 * tid + 1]);
}

// ---------------------------------------------------------------------------
// Robust per-element logsumexp (cold fallbacks only)
// ---------------------------------------------------------------------------
__device__ __noinline__ float robust_lp(float x, float q, int t, int K) {
    float m = -3.0e38f;
    for (int r = 0; r < K; ++r) {
        float arg = fmaf(g_C2[r], q, fmaf(g_B2t[r][t], x, g_A2t[r][t]));
        m = fmaxf(m, arg);
    }
    float s = 0.0f;
    for (int r = 0; r < K; ++r) {
        float arg = fmaf(g_C2[r], q, fmaf(g_B2t[r][t], x, g_A2t[r][t]));
        s += ex2f(arg - m);
    }
    return LN2_F * (m + lg2f_(s));
}

// Cold A handler (provably unreachable for c>=48; kept for safety).
__device__ __noinline__ float coldA(const float4* __restrict__ X4,
                                    int tid, int c, int K) {
    float acc = 0.0f;
    for (int k = 0; k < A_ITEMS; ++k) {
        float4 xv = X4[tid + k * A_STRIDE];
        int t0 = c * 4;
        acc += robust_lp(xv.x, xv.x * xv.x, t0,     K);
        acc += robust_lp(xv.y, xv.y * xv.y, t0 + 1, K);
        acc += robust_lp(xv.z, xv.z * xv.z, t0 + 2, K);
        acc += robust_lp(xv.w, xv.w * xv.w, t0 + 3, K);
    }
    return acc - (float)(4 * A_ITEMS) * HALF_LOG_2PI;
}

// ---------------------------------------------------------------------------
// Fused main. Blocks [0,192): B path (t<192), c-coherent warps, balanced
// interleave, MUFU ex2. Blocks [192,704): A path — 32 items/thread in 8
// double-buffered batches of 4: loads for batch i+1 issued before computing
// batch i, so >=4 LDG in flight per thread for the whole kernel (continuous
// DRAM streaming, no burst-drain). Strided coalesced layout, c = tid & 511
// constant per thread. Deterministic fused fixed-order tail.
// ---------------------------------------------------------------------------
__global__ void __launch_bounds__(THREADS) k_main(const float* __restrict__ X,
                                                  float* __restrict__ out) {
    __shared__ float4 sA[R][CSPLIT];
    __shared__ float  sD[R], sC[R];
    __shared__ int    sK[CSPLIT];
    __shared__ float  sred[THREADS];
    __shared__ bool   s_last;

    const float4* X4 = (const float4*)X;
    const float4* A4 = (const float4*)g_A2t;
    const int th = threadIdx.x;
    float acc = 0.0f;

    if (blockIdx.x < B_BLOCKS) {
        // ---------------- B path: t < 192 ----------------
        #pragma unroll
        for (int j = 0; j < (R * CSPLIT + THREADS - 1) / THREADS; ++j) {
            int e = th + j * THREADS;
            if (e < R * CSPLIT) {
                int r = e / CSPLIT, c = e - r * CSPLIT;
                sA[r][c] = A4[r * L4 + c];
            }
        }
        if (th < R) { sD[th] = g_D[th]; sC[th] = g_C2[th]; }
        if (th < CSPLIT) sK[th] = g_Kt4[th];
        __syncthreads();

        const int lane = th & 31;
        const int W = blockIdx.x * 8 + (th >> 5);
        const int idx = W % CSPLIT;
        const int c = (idx & 1) ? (CSPLIT - 1 - (idx >> 1)) : (idx >> 1);
        const int ng = W / CSPLIT;

        float4 xv[8];
        #pragma unroll
        for (int it = 0; it < 8; ++it) {
            int n = ng * 256 + it * 32 + lane;
            xv[it] = __ldcs(&X4[n * L4 + c]);
        }

        const int K = sK[c];
        const float t0f = (float)(4 * c);

        #pragma unroll 1
        for (int it = 0; it < 8; ++it) {
            float x0 = xv[it].x, x1 = xv[it].y, x2 = xv[it].z, x3 = xv[it].w;
            float q0 = x0 * x0, q1 = x1 * x1, q2 = x2 * x2, q3 = x3 * x3;
            float S0 = 0.f, S1 = 0.f, S2 = 0.f, S3 = 0.f;
            #pragma unroll 2
            for (int r = 0; r < K; ++r) {
                float4 ar = sA[r][c];
                float d  = sD[r];
                float cr = sC[r];
                float b0 = d * t0f, b1 = b0 + d, b2 = b1 + d, b3 = b2 + d;
                S0 += ex2f(fmaf(cr, q0, fmaf(b0, x0, ar.x)));
                S1 += ex2f(fmaf(cr, q1, fmaf(b1, x1, ar.y)));
                S2 += ex2f(fmaf(cr, q2, fmaf(b2, x2, ar.z)));
                S3 += ex2f(fmaf(cr, q3, fmaf(b3, x3, ar.w)));
            }
            float smin = fminf(fminf(S0, S1), fminf(S2, S3));
            if (smin > 1e-30f) {
                acc += LN2_F * (lg2f_(S0) + lg2f_(S1) + lg2f_(S2) + lg2f_(S3));
            } else {
                int tt = c * 4;
                acc += robust_lp(x0, q0, tt,     K);
                acc += robust_lp(x1, q1, tt + 1, K);
                acc += robust_lp(x2, q2, tt + 2, K);
                acc += robust_lp(x3, q3, tt + 3, K);
            }
            acc -= 4.0f * HALF_LOG_2PI;
        }
    } else {
        // ---------------- A path: t >= 192, pipelined streaming ----------------
        const float4* B4 = (const float4*)g_B2t;
        const int tid = (blockIdx.x - B_BLOCKS) * THREADS + th;   // 0..131071
        const int c = tid & (L4 - 1);

        if (c >= CSPLIT) {
            const int K = g_Kt4[c];
            if (K != 1) {
                acc = coldA(X4, tid, c, K);   // unreachable safety path
            } else {
                const float4 a = A4[c];
                const float4 b = B4[c];
                const float cc = g_C2[0];

                float4 u[4], v[4];
                #pragma unroll
                for (int j = 0; j < 4; ++j)
                    u[j] = __ldcs(&X4[tid + j * A_STRIDE]);

                float s = 0.0f;
                #pragma unroll
                for (int seg = 0; seg < A_ITEMS / 4; ++seg) {
                    float4* cur = (seg & 1) ? v : u;
                    float4* nxt = (seg & 1) ? u : v;
                    if (seg < A_ITEMS / 4 - 1) {
                        #pragma unroll
                        for (int j = 0; j < 4; ++j)
                            nxt[j] = __ldcs(&X4[tid + ((seg + 1) * 4 + j) * A_STRIDE]);
                    }
                    #pragma unroll
                    for (int j = 0; j < 4; ++j) {
                        float x0 = cur[j].x, x1 = cur[j].y, x2 = cur[j].z, x3 = cur[j].w;
                        float g0 = fmaf(cc, x0 * x0, fmaf(b.x, x0, a.x));
                        float g1 = fmaf(cc, x1 * x1, fmaf(b.y, x1, a.y));
                        float g2 = fmaf(cc, x2 * x2, fmaf(b.z, x2, a.z));
                        float g3 = fmaf(cc, x3 * x3, fmaf(b.w, x3, a.w));
                        s += (g0 + g1) + (g2 + g3);
                    }
                }
                acc = LN2_F * s - (float)(4 * A_ITEMS) * HALF_LOG_2PI;
            }
        }
        __syncthreads();   // mirror B path's post-load sync (uniform per block)
    }

    // ---------------- fused deterministic tail ----------------
    sred[th] = acc;
    __syncthreads();
    for (int s = THREADS / 2; s > 0; s >>= 1) {
        if (th < s) sred[th] += sred[th + s];
        __syncthreads();
    }
    if (th == 0) {
        g_partial[blockIdx.x] = sred[0];
        __threadfence();
        unsigned n = atomicAdd(&g_count, 1u);
        s_last = (n == TOTAL_BLOCKS - 1);
    }
    __syncthreads();

    if (s_last) {
        __threadfence();
        float v = 0.0f;
        for (int idx = th; idx < TOTAL_BLOCKS; idx += THREADS)
            v += g_partial[idx];
        sred[th] = v;
        __syncthreads();
        for (int s = THREADS / 2; s > 0; s >>= 1) {
            if (th < s) sred[th] += sred[th + s];
            __syncthreads();
        }
        if (th == 0) out[0] = sred[0] / (float)NSEQ;
    }
}

// ---------------------------------------------------------------------------
extern "C" void kernel_launch(void* const* d_in, const int* in_sizes, int n_in,
                              void* d_out, int out_size) {
    const float* X       = (const float*)d_in[0];
    const float* Tr      = (const float*)d_in[1];
    const float* init_w  = (const float*)d_in[2];
    const float* sig     = (const float*)d_in[3];
    const float* mu_rate = (const float*)d_in[4];
    float* out = (float*)d_out;

    k_prep<<<128, 256>>>(Tr, init_w, sig, mu_rate);
    k_main<<<TOTAL_BLOCKS, THREADS>>>(X, out);
}

// round 14
// speedup vs baseline: 1.3789x; 1.0387x over previous
#include <cuda_runtime.h>
#include <math.h>

#define R 32
#define PB 36              /* padded smem row stride */
#define L 2048
#define NSEQ 8192
#define NL (NSEQ * L)
#define NL4 (NL / 4)       /* 4194304 */
#define L4 (L / 4)         /* 512     */

#define CSPLIT 48          /* t < 192 -> B path */

#define THREADS 256
#define B_BLOCKS 192
#define A_BLOCKS 256
#define A_ITEMS 64         /* 256*256*64 = NL4 */
#define A_STRIDE (A_BLOCKS * THREADS)   /* 65536, multiple of L4 */
#define TOTAL_BLOCKS (B_BLOCKS + A_BLOCKS)   /* 448 -> single wave */

__device__ float    g_A2t[R][L];
__device__ float    g_B2t[R][L];
__device__ float    g_C2[R];
__device__ float    g_D[R];
__device__ int      g_Kt4[L4];
__device__ float    g_partial[TOTAL_BLOCKS];
__device__ unsigned g_count;

__device__ __forceinline__ float ex2f(float x) {
    float y; asm("ex2.approx.f32 %0, %1;" : "=f"(y) : "f"(x)); return y;
}
__device__ __forceinline__ float lg2f_(float x) {
    float y; asm("lg2.approx.f32 %0, %1;" : "=f"(y) : "f"(x)); return y;
}

#define LN2_F 0.69314718055994531f
#define INV_LN2_F 1.44269504088896340f
#define HALF_LOG_2PI 0.91893853320467274f
#define DROP_THRESH (-18.0f)
#define XLO (-8.0f)
#define XHI (8.0f)

// ---------------------------------------------------------------------------
// k_prep: proven. 128 blocks x 256 threads; block b emits tables for t in
// [16b,16b+16). h_t == stationary pi for t >= 64 (Doeblin ~0.5).
// ---------------------------------------------------------------------------
__global__ void __launch_bounds__(256) k_prep(const float* __restrict__ Tr,
                                              const float* __restrict__ init_w,
                                              const float* __restrict__ sig,
                                              const float* __restrict__ mu_rates) {
    __shared__ float P[6][R][PB];
    __shared__ float hs[8][R];
    __shared__ float pi_s[R];
    __shared__ int   karr[8];
    const int tid  = threadIdx.x;
    const int w    = tid >> 5, lane = tid & 31;
    const int rw   = tid >> 3, seg = (tid & 7) * 4;
    const int b    = blockIdx.x;

    if (b == 0 && tid == 0) g_count = 0u;

    *(float4*)&P[0][rw][seg] = ((const float4*)Tr)[tid];
    __syncthreads();

    #pragma unroll 1
    for (int k = 1; k < 6; ++k) {
        float4 a0 = make_float4(0.f, 0.f, 0.f, 0.f);
        float4 a1 = make_float4(0.f, 0.f, 0.f, 0.f);
        #pragma unroll
        for (int j = 0; j < R; j += 2) {
            float  r0 = P[k - 1][rw][j];
            float4 b0 = *(const float4*)&P[k - 1][j][seg];
            a0.x = fmaf(r0, b0.x, a0.x); a0.y = fmaf(r0, b0.y, a0.y);
            a0.z = fmaf(r0, b0.z, a0.z); a0.w = fmaf(r0, b0.w, a0.w);
            float  r1 = P[k - 1][rw][j + 1];
            float4 b1 = *(const float4*)&P[k - 1][j + 1][seg];
            a1.x = fmaf(r1, b1.x, a1.x); a1.y = fmaf(r1, b1.y, a1.y);
            a1.z = fmaf(r1, b1.z, a1.z); a1.w = fmaf(r1, b1.w, a1.w);
        }
        float4 acc = make_float4(a0.x + a1.x, a0.y + a1.y, a0.z + a1.z, a0.w + a1.w);
        *(float4*)&P[k][rw][seg] = acc;
        __syncthreads();
    }

    if (w == 0) {
        hs[0][lane] = init_w[lane];
        __syncwarp();
        #pragma unroll 1
        for (int rep = 0; rep < 2; ++rep) {
            float a0 = 0.f, a1 = 0.f, a2 = 0.f, a3 = 0.f;
            #pragma unroll
            for (int j = 0; j < R; j += 4) {
                a0 = fmaf(hs[0][j    ], P[5][j    ][lane], a0);
                a1 = fmaf(hs[0][j + 1], P[5][j + 1][lane], a1);
                a2 = fmaf(hs[0][j + 2], P[5][j + 2][lane], a2);
                a3 = fmaf(hs[0][j + 3], P[5][j + 3][lane], a3);
            }
            float v = (a0 + a1) + (a2 + a3);
            __syncwarp();
            hs[0][lane] = v;
            __syncwarp();
        }
        pi_s[lane] = hs[0][lane];
    }
    __syncthreads();

    float sg     = sig[lane];
    float inv_s2 = 1.0f / (sg * sg);
    float l2sig  = lg2f_(sg);
    float mr     = mu_rates[lane];
    float C2     = -0.5f * inv_s2 * INV_LN2_F;
    if (b == 0 && w == 0) {
        g_C2[lane] = C2;
        g_D[lane]  = mr * inv_s2 * INV_LN2_F;
    }

    int kloc = 1;
    #pragma unroll 1
    for (int i = 0; i < 2; ++i) {
        int t = b * 16 + w * 2 + i;
        if (t < 64) {
            hs[w][lane] = init_w[lane];
            __syncwarp();
            #pragma unroll 1
            for (int k = 0; k < 6; ++k) {
                if ((t >> k) & 1) {
                    float a0 = 0.f, a1 = 0.f, a2 = 0.f, a3 = 0.f;
                    #pragma unroll
                    for (int j = 0; j < R; j += 4) {
                        a0 = fmaf(hs[w][j    ], P[k][j    ][lane], a0);
                        a1 = fmaf(hs[w][j + 1], P[k][j + 1][lane], a1);
                        a2 = fmaf(hs[w][j + 2], P[k][j + 2][lane], a2);
                        a3 = fmaf(hs[w][j + 3], P[k][j + 3][lane], a3);
                    }
                    float v = (a0 + a1) + (a2 + a3);
                    __syncwarp();
                    hs[w][lane] = v;
                    __syncwarp();
                }
            }
        } else {
            hs[w][lane] = pi_s[lane];
            __syncwarp();
        }

        float sum = 0.0f;
        #pragma unroll
        for (int j = 0; j < R; ++j) sum += hs[w][j];
        float lm2 = lg2f_(hs[w][lane]) - lg2f_(sum);

        float mu = (float)t * mr;
        float B2 = mu * inv_s2 * INV_LN2_F;
        float A2 = lm2 - l2sig - 0.5f * mu * mu * inv_s2 * INV_LN2_F;
        g_A2t[lane][t] = A2;
        g_B2t[lane][t] = B2;

        float A0 = __shfl_sync(0xffffffffu, A2, 0);
        float B0 = __shfl_sync(0xffffffffu, B2, 0);
        float C0 = __shfl_sync(0xffffffffu, C2, 0);
        float dA = A2 - A0, dB = B2 - B0, dC = C2 - C0;
        float d1 = dA + dB * XLO + dC * XLO * XLO;
        float d2 = dA + dB * XHI + dC * XHI * XHI;
        float dmax = fmaxf(d1, d2);
        if (fabsf(dC) > 1e-20f) {
            float xv = -dB / (2.0f * dC);
            if (xv > XLO && xv < XHI) dmax = fmaxf(dmax, dA + dB * xv + dC * xv * xv);
        }
        bool keep = (dmax >= DROP_THRESH);
        unsigned bm = __ballot_sync(0xffffffffu, keep);
        int K = 32 - __clz(bm);
        kloc = max(kloc, K);
    }
    if (lane == 0) karr[w] = kloc;
    __syncthreads();
    if (tid < 4)
        g_Kt4[b * 4 + tid] = max(karr[2 * tid], karr[2 * tid + 1]);
}

// ---------------------------------------------------------------------------
// Robust per-element logsumexp (cold fallbacks only)
// ---------------------------------------------------------------------------
__device__ __noinline__ float robust_lp(float x, float q, int t, int K) {
    float m = -3.0e38f;
    for (int r = 0; r < K; ++r) {
        float arg = fmaf(g_C2[r], q, fmaf(g_B2t[r][t], x, g_A2t[r][t]));
        m = fmaxf(m, arg);
    }
    float s = 0.0f;
    for (int r = 0; r < K; ++r) {
        float arg = fmaf(g_C2[r], q, fmaf(g_B2t[r][t], x, g_A2t[r][t]));
        s += ex2f(arg - m);
    }
    return LN2_F * (m + lg2f_(s));
}

// Cold A handler (provably unreachable for c>=48; kept for safety).
__device__ __noinline__ float coldA(const float4* __restrict__ X4,
                                    int tid, int c, int K) {
    float acc = 0.0f;
    for (int k = 0; k < A_ITEMS; ++k) {
        float4 xv = X4[tid + k * A_STRIDE];
        int t0 = c * 4;
        acc += robust_lp(xv.x, xv.x * xv.x, t0,     K);
        acc += robust_lp(xv.y, xv.y * xv.y, t0 + 1, K);
        acc += robust_lp(xv.z, xv.z * xv.z, t0 + 2, K);
        acc += robust_lp(xv.w, xv.w * xv.w, t0 + 3, K);
    }
    return acc - (float)(4 * A_ITEMS) * HALF_LOG_2PI;
}

// ---------------------------------------------------------------------------
// Fused main, SINGLE WAVE (448 blocks <= ~4 resident/SM * 148). Blocks
// [0,192): B path (t<192), c-coherent warps, balanced interleave, MUFU ex2.
// Blocks [192,448): A path — 64 items/thread in 16 double-buffered batches
// of 4 (>=4 LDG always in flight; continuous streaming start-to-finish, no
// wave transition, B's MUFU overlaps A's DRAM stream). Strided coalesced
// layout, c = tid & 511 constant per thread. Deterministic fixed-order tail.
// ---------------------------------------------------------------------------
__global__ void __launch_bounds__(THREADS) k_main(const float* __restrict__ X,
                                                  float* __restrict__ out) {
    __shared__ float4 sA[R][CSPLIT];
    __shared__ float  sD[R], sC[R];
    __shared__ int    sK[CSPLIT];
    __shared__ float  sred[THREADS];
    __shared__ bool   s_last;

    const float4* X4 = (const float4*)X;
    const float4* A4 = (const float4*)g_A2t;
    const int th = threadIdx.x;
    float acc = 0.0f;

    if (blockIdx.x < B_BLOCKS) {
        // ---------------- B path: t < 192 ----------------
        #pragma unroll
        for (int j = 0; j < (R * CSPLIT + THREADS - 1) / THREADS; ++j) {
            int e = th + j * THREADS;
            if (e < R * CSPLIT) {
                int r = e / CSPLIT, c = e - r * CSPLIT;
                sA[r][c] = A4[r * L4 + c];
            }
        }
        if (th < R) { sD[th] = g_D[th]; sC[th] = g_C2[th]; }
        if (th < CSPLIT) sK[th] = g_Kt4[th];
        __syncthreads();

        const int lane = th & 31;
        const int W = blockIdx.x * 8 + (th >> 5);
        const int idx = W % CSPLIT;
        const int c = (idx & 1) ? (CSPLIT - 1 - (idx >> 1)) : (idx >> 1);
        const int ng = W / CSPLIT;

        float4 xv[8];
        #pragma unroll
        for (int it = 0; it < 8; ++it) {
            int n = ng * 256 + it * 32 + lane;
            xv[it] = __ldcs(&X4[n * L4 + c]);
        }

        const int K = sK[c];
        const float t0f = (float)(4 * c);

        #pragma unroll 1
        for (int it = 0; it < 8; ++it) {
            float x0 = xv[it].x, x1 = xv[it].y, x2 = xv[it].z, x3 = xv[it].w;
            float q0 = x0 * x0, q1 = x1 * x1, q2 = x2 * x2, q3 = x3 * x3;
            float S0 = 0.f, S1 = 0.f, S2 = 0.f, S3 = 0.f;
            #pragma unroll 2
            for (int r = 0; r < K; ++r) {
                float4 ar = sA[r][c];
                float d  = sD[r];
                float cr = sC[r];
                float b0 = d * t0f, b1 = b0 + d, b2 = b1 + d, b3 = b2 + d;
                S0 += ex2f(fmaf(cr, q0, fmaf(b0, x0, ar.x)));
                S1 += ex2f(fmaf(cr, q1, fmaf(b1, x1, ar.y)));
                S2 += ex2f(fmaf(cr, q2, fmaf(b2, x2, ar.z)));
                S3 += ex2f(fmaf(cr, q3, fmaf(b3, x3, ar.w)));
            }
            float smin = fminf(fminf(S0, S1), fminf(S2, S3));
            if (smin > 1e-30f) {
                acc += LN2_F * (lg2f_(S0) + lg2f_(S1) + lg2f_(S2) + lg2f_(S3));
            } else {
                int tt = c * 4;
                acc += robust_lp(x0, q0, tt,     K);
                acc += robust_lp(x1, q1, tt + 1, K);
                acc += robust_lp(x2, q2, tt + 2, K);
                acc += robust_lp(x3, q3, tt + 3, K);
            }
            acc -= 4.0f * HALF_LOG_2PI;
        }
    } else {
        // ---------------- A path: t >= 192, pipelined streaming ----------------
        const float4* B4 = (const float4*)g_B2t;
        const int tid = (blockIdx.x - B_BLOCKS) * THREADS + th;   // 0..65535
        const int c = tid & (L4 - 1);

        if (c >= CSPLIT) {
            const int K = g_Kt4[c];
            if (K != 1) {
                acc = coldA(X4, tid, c, K);   // unreachable safety path
            } else {
                const float4 a = A4[c];
                const float4 b = B4[c];
                const float cc = g_C2[0];

                float4 u[4], v[4];
                #pragma unroll
                for (int j = 0; j < 4; ++j)
                    u[j] = __ldcs(&X4[tid + j * A_STRIDE]);

                float s = 0.0f;
                #pragma unroll 1
                for (int seg = 0; seg < A_ITEMS / 4; ++seg) {
                    float4* cur = (seg & 1) ? v : u;
                    float4* nxt = (seg & 1) ? u : v;
                    if (seg < A_ITEMS / 4 - 1) {
                        #pragma unroll
                        for (int j = 0; j < 4; ++j)
                            nxt[j] = __ldcs(&X4[tid + ((seg + 1) * 4 + j) * A_STRIDE]);
                    }
                    #pragma unroll
                    for (int j = 0; j < 4; ++j) {
                        float x0 = cur[j].x, x1 = cur[j].y, x2 = cur[j].z, x3 = cur[j].w;
                        float g0 = fmaf(cc, x0 * x0, fmaf(b.x, x0, a.x));
                        float g1 = fmaf(cc, x1 * x1, fmaf(b.y, x1, a.y));
                        float g2 = fmaf(cc, x2 * x2, fmaf(b.z, x2, a.z));
                        float g3 = fmaf(cc, x3 * x3, fmaf(b.w, x3, a.w));
                        s += (g0 + g1) + (g2 + g3);
                    }
                }
                acc = LN2_F * s - (float)(4 * A_ITEMS) * HALF_LOG_2PI;
            }
        }
        __syncthreads();   // mirror B path's post-load sync (uniform per block)
    }

    // ---------------- fused deterministic tail ----------------
    sred[th] = acc;
    __syncthreads();
    for (int s = THREADS / 2; s > 0; s >>= 1) {
        if (th < s) sred[th] += sred[th + s];
        __syncthreads();
    }
    if (th == 0) {
        g_partial[blockIdx.x] = sred[0];
        __threadfence();
        unsigned n = atomicAdd(&g_count, 1u);
        s_last = (n == TOTAL_BLOCKS - 1);
    }
    __syncthreads();

    if (s_last) {
        __threadfence();
        float v = 0.0f;
        for (int idx = th; idx < TOTAL_BLOCKS; idx += THREADS)
            v += g_partial[idx];
        sred[th] = v;
        __syncthreads();
        for (int s = THREADS / 2; s > 0; s >>= 1) {
            if (th < s) sred[th] += sred[th + s];
            __syncthreads();
        }
        if (th == 0) out[0] = sred[0] / (float)NSEQ;
    }
}

// ---------------------------------------------------------------------------
extern "C" void kernel_launch(void* const* d_in, const int* in_sizes, int n_in,
                              void* d_out, int out_size) {
    const float* X       = (const float*)d_in[0];
    const float* Tr      = (const float*)d_in[1];
    const float* init_w  = (const float*)d_in[2];
    const float* sig     = (const float*)d_in[3];
    const float* mu_rate = (const float*)d_in[4];
    float* out = (float*)d_out;

    k_prep<<<128, 256>>>(Tr, init_w, sig, mu_rate);
    k_main<<<TOTAL_BLOCKS, THREADS>>>(X, out);
}